// round 11
// baseline (speedup 1.0000x reference)
#include <cuda_runtime.h>
#include <cstdint>

#define N_NODES 100000
#define N_EDGES 1600000
#define F 256          // IN_FEATS == H_FEATS
#define C 64           // NUM_CLASSES

// ---------------- scratch (static device globals; no allocation) -------------
__device__ int      g_deg_out[N_NODES];
__device__ int      g_deg_in[N_NODES];
__device__ float    g_rs_out[N_NODES];            // rsqrt(max(deg_out,1))
__device__ unsigned g_x32[(size_t)N_NODES * F];   // x pre-converted to tf32
__device__ unsigned g_w32[(size_t)F * F];         // W pre-converted to tf32
__device__ float    g_h[(size_t)N_NODES * F];     // x @ W  (unscaled)
__device__ float    g_pooled[F];
__device__ int      g_is64;
// CSR-by-dst
__device__ int   g_row_ptr[N_NODES + 1];
__device__ int   g_cursor[N_NODES];
__device__ int   g_edge_src[N_EDGES];
#define SCAN_BLOCKS 1024
__device__ int   g_blocksum[SCAN_BLOCKS];
__device__ int   g_blockoff[SCAN_BLOCKS];

// ---------------- K-1: index dtype probe --------------------------------------
__global__ void detect_kernel(const unsigned int* __restrict__ words) {
    __shared__ int nonzero;
    if (threadIdx.x == 0) nonzero = 0;
    __syncthreads();
    for (int p = threadIdx.x; p < 1024; p += blockDim.x)
        if (words[2 * p + 1] != 0u) atomicOr(&nonzero, 1);
    __syncthreads();
    if (threadIdx.x == 0) g_is64 = (nonzero == 0) ? 1 : 0;
}

__device__ __forceinline__ int load_idx(const void* p, int i, int is64) {
    return is64 ? (int)((const long long*)p)[i] : ((const int*)p)[i];
}

__device__ __forceinline__ unsigned f2tf32(float f) {
    unsigned u;
    asm("cvt.rna.tf32.f32 %0, %1;" : "=r"(u) : "f"(f));
    return u;
}

// ---------------- tf32 pre-conversion kernels ---------------------------------
__global__ void xcvt_kernel(const float* __restrict__ x, long long total4) {
    long long tid    = (long long)blockIdx.x * blockDim.x + threadIdx.x;
    long long stride = (long long)gridDim.x * blockDim.x;
    uint4* o = reinterpret_cast<uint4*>(g_x32);
    const float4* in = reinterpret_cast<const float4*>(x);
    for (long long i = tid; i < total4; i += stride) {
        float4 v = in[i];
        uint4 u;
        u.x = f2tf32(v.x); u.y = f2tf32(v.y); u.z = f2tf32(v.z); u.w = f2tf32(v.w);
        o[i] = u;
    }
}

__global__ void wcvt_kernel(const float* __restrict__ W) {
    int i = blockIdx.x * blockDim.x + threadIdx.x;   // over F*F/4
    const float4* in = reinterpret_cast<const float4*>(W);
    uint4* o = reinterpret_cast<uint4*>(g_w32);
    if (i < F * F / 4) {
        float4 v = in[i];
        uint4 u;
        u.x = f2tf32(v.x); u.y = f2tf32(v.y); u.z = f2tf32(v.z); u.w = f2tf32(v.w);
        o[i] = u;
    }
}

// ---------------- K0: zero scratch -------------------------------------------
__global__ void zero_kernel(int nodes) {
    int tid    = blockIdx.x * blockDim.x + threadIdx.x;
    int stride = gridDim.x * blockDim.x;
    for (int i = tid; i < nodes; i += stride) {
        g_deg_out[i] = 0;
        g_deg_in[i]  = 0;
    }
    if (tid < F) g_pooled[tid] = 0.f;
}

// ---------------- K1: degree counts ------------------------------------------
__global__ void deg_kernel(const void* __restrict__ src,
                           const void* __restrict__ dst, int nE) {
    int i = blockIdx.x * blockDim.x + threadIdx.x;
    int is64 = g_is64;
    if (i < nE) {
        atomicAdd(&g_deg_out[load_idx(src, i, is64)], 1);
        atomicAdd(&g_deg_in[load_idx(dst, i, is64)], 1);
    }
}

__global__ void rs_kernel(int nodes) {
    int i = blockIdx.x * blockDim.x + threadIdx.x;
    if (i < nodes) g_rs_out[i] = rsqrtf((float)max(g_deg_out[i], 1));
}

// ---------------- CSR build: 3-phase block scan of deg_in --------------------
__global__ void scan_a_kernel(int nodes) {
    __shared__ int s[256];
    int i = blockIdx.x * 256 + threadIdx.x;
    s[threadIdx.x] = (i < nodes) ? g_deg_in[i] : 0;
    __syncthreads();
#pragma unroll
    for (int off = 128; off > 0; off >>= 1) {
        if (threadIdx.x < off) s[threadIdx.x] += s[threadIdx.x + off];
        __syncthreads();
    }
    if (threadIdx.x == 0) g_blocksum[blockIdx.x] = s[0];
}

__global__ void scan_b_kernel(int nblocks) {
    __shared__ int s[SCAN_BLOCKS];
    int t = threadIdx.x;
    s[t] = (t < nblocks) ? g_blocksum[t] : 0;
    __syncthreads();
#pragma unroll
    for (int off = 1; off < SCAN_BLOCKS; off <<= 1) {
        int v = (t >= off) ? s[t - off] : 0;
        __syncthreads();
        s[t] += v;
        __syncthreads();
    }
    if (t < nblocks) g_blockoff[t] = (t == 0) ? 0 : s[t - 1];
}

__global__ void scan_c_kernel(int nodes) {
    __shared__ int s[256];
    int i = blockIdx.x * 256 + threadIdx.x;
    int t = threadIdx.x;
    int d = (i < nodes) ? g_deg_in[i] : 0;
    s[t] = d;
    __syncthreads();
#pragma unroll
    for (int off = 1; off < 256; off <<= 1) {
        int v = (t >= off) ? s[t - off] : 0;
        __syncthreads();
        s[t] += v;
        __syncthreads();
    }
    int excl = g_blockoff[blockIdx.x] + s[t] - d;
    if (i < nodes) {
        g_row_ptr[i] = excl;
        g_cursor[i]  = excl;
        if (i == nodes - 1) g_row_ptr[nodes] = excl + d;
    }
}

__global__ void scatter_kernel(const void* __restrict__ src,
                               const void* __restrict__ dst, int nE) {
    int i = blockIdx.x * blockDim.x + threadIdx.x;
    int is64 = g_is64;
    if (i < nE) {
        int d = load_idx(dst, i, is64);
        int pos = atomicAdd(&g_cursor[d], 1);
        g_edge_src[pos] = load_idx(src, i, is64);
    }
}

// ---------------- K2: TF32 tensor-core GEMM  h = x @ W -----------------------
// Operands are PRE-CONVERTED tf32 (g_x32 / g_w32) — zero cvt in the hot loop.
// 128x128 block tile, BK=16 (2 k-steps of 8), 8 warps as 4(m) x 2(n).
// Smem holds fragment-permuted tiles; frag loads are conflict-free LDS.64.
#define TBM 128
#define TBN 128
#define TBK 16

__device__ __forceinline__ void mma_tf32(float c[4], const unsigned a[4], const unsigned b[2]) {
    asm volatile(
        "mma.sync.aligned.m16n8k8.row.col.f32.tf32.tf32.f32 "
        "{%0,%1,%2,%3}, {%4,%5,%6,%7}, {%8,%9}, {%0,%1,%2,%3};"
        : "+f"(c[0]), "+f"(c[1]), "+f"(c[2]), "+f"(c[3])
        : "r"(a[0]), "r"(a[1]), "r"(a[2]), "r"(a[3]), "r"(b[0]), "r"(b[1]));
}

__global__ __launch_bounds__(256, 1) void gemm_tc_kernel(int M) {
    __shared__ unsigned As[8][4][32][2];    // 8KB
    __shared__ unsigned Bs[16][2][32][2];   // 8KB

    const int t      = threadIdx.x;
    const int lane   = t & 31;
    const int wid    = t >> 5;
    const int warp_m = wid & 3;
    const int warp_n = wid >> 2;
    const int bm     = blockIdx.x * TBM;
    const int bn     = blockIdx.y * TBN;

    const int aRow  = t >> 2;            // 0..63 (+64)
    const int aKc4  = (t & 3) << 2;      // 0,4,8,12
    const int bK    = t >> 5;            // 0..7 (+8)
    const int bNc4  = (t & 31) << 2;     // 0..124

    float acc[2][8][4];
#pragma unroll
    for (int i = 0; i < 2; i++)
#pragma unroll
        for (int j = 0; j < 8; j++)
#pragma unroll
            for (int r = 0; r < 4; r++) acc[i][j][r] = 0.f;

    const int g = lane >> 2;
    const int tg = lane & 3;
    const int laneq = tg * 8 + g;

    for (int k0 = 0; k0 < F; k0 += TBK) {
        // ---- A tile (pre-converted): permuted store ----
        {
            const int kstep = aKc4 >> 3;
            const int cch   = (aKc4 & 7) >> 2;
#pragma unroll
            for (int half = 0; half < 2; half++) {
                int r = aRow + half * 64;
                uint4 av = make_uint4(0u, 0u, 0u, 0u);
                if (bm + r < M)
                    av = *reinterpret_cast<const uint4*>(g_x32 + (size_t)(bm + r) * F + k0 + aKc4);
                int m16  = r >> 4;
                int rlo  = r & 15;
                int reg  = ((rlo >= 8) ? 1 : 0) + 2 * cch;
                int lb   = (rlo & 7) * 4;
                As[m16][reg][lb + 0][kstep] = av.x;
                As[m16][reg][lb + 1][kstep] = av.y;
                As[m16][reg][lb + 2][kstep] = av.z;
                As[m16][reg][lb + 3][kstep] = av.w;
            }
        }
        // ---- B tile (pre-converted): permuted store ----
        {
#pragma unroll
            for (int half = 0; half < 2; half++) {
                int k = bK + half * 8;
                uint4 bv = *reinterpret_cast<const uint4*>(g_w32 + (size_t)(k0 + k) * F + bn + bNc4);
                int kstep = k >> 3;
                int kk    = k & 7;
                int reg   = (kk >= 4) ? 1 : 0;
                int tgk   = kk & 3;
                int n8    = bNc4 >> 3;
                int gb    = bNc4 & 7;
                Bs[n8][reg][tgk * 8 + gb + 0][kstep] = bv.x;
                Bs[n8][reg][tgk * 8 + gb + 1][kstep] = bv.y;
                Bs[n8][reg][tgk * 8 + gb + 2][kstep] = bv.z;
                Bs[n8][reg][tgk * 8 + gb + 3][kstep] = bv.w;
            }
        }
        __syncthreads();

        unsigned afr[2][2][4];
        unsigned bfr[8][2][2];
#pragma unroll
        for (int mi = 0; mi < 2; mi++) {
            int m16 = warp_m * 2 + mi;
#pragma unroll
            for (int r = 0; r < 4; r++) {
                uint2 v = *reinterpret_cast<const uint2*>(&As[m16][r][lane][0]);
                afr[mi][0][r] = v.x;
                afr[mi][1][r] = v.y;
            }
        }
#pragma unroll
        for (int ni = 0; ni < 8; ni++) {
            int n8 = warp_n * 8 + ni;
#pragma unroll
            for (int r = 0; r < 2; r++) {
                uint2 v = *reinterpret_cast<const uint2*>(&Bs[n8][r][laneq][0]);
                bfr[ni][0][r] = v.x;
                bfr[ni][1][r] = v.y;
            }
        }

#pragma unroll
        for (int ks = 0; ks < 2; ks++)
#pragma unroll
            for (int mi = 0; mi < 2; mi++)
#pragma unroll
                for (int ni = 0; ni < 8; ni++)
                    mma_tf32(acc[mi][ni], afr[mi][ks], bfr[ni][ks]);

        __syncthreads();
    }

#pragma unroll
    for (int mi = 0; mi < 2; mi++) {
        int rowA = bm + warp_m * 32 + mi * 16 + g;
        int rowB = rowA + 8;
#pragma unroll
        for (int ni = 0; ni < 8; ni++) {
            int col = bn + warp_n * 64 + ni * 8 + tg * 2;
            if (rowA < M)
                *reinterpret_cast<float2*>(g_h + (size_t)rowA * F + col) =
                    make_float2(acc[mi][ni][0], acc[mi][ni][1]);
            if (rowB < M)
                *reinterpret_cast<float2*>(g_h + (size_t)rowB * F + col) =
                    make_float2(acc[mi][ni][2], acc[mi][ni][3]);
        }
    }
}

// ---------------- K3: CSR aggregate + epilogue + pool -------------------------
__global__ __launch_bounds__(256) void agg_kernel(const float* __restrict__ b,
                                                  int nodes) {
    __shared__ float pooled_s[F];
    if (threadIdx.x < F) pooled_s[threadIdx.x] = 0.f;
    __syncthreads();

    int warp = (blockIdx.x * blockDim.x + threadIdx.x) >> 5;
    int lane = threadIdx.x & 31;

    if (warp < nodes) {
        int begin = g_row_ptr[warp];
        int end   = g_row_ptr[warp + 1];

        float4 a0 = make_float4(0.f, 0.f, 0.f, 0.f);
        float4 a1 = make_float4(0.f, 0.f, 0.f, 0.f);

        int e = begin;
        for (; e + 1 < end; e += 2) {
            int s0 = g_edge_src[e];
            int s1 = g_edge_src[e + 1];
            float w0 = g_rs_out[s0];
            float w1 = g_rs_out[s1];
            const float4* r0 = reinterpret_cast<const float4*>(g_h + (size_t)s0 * F);
            const float4* r1 = reinterpret_cast<const float4*>(g_h + (size_t)s1 * F);
            float4 v00 = r0[lane], v01 = r0[lane + 32];
            float4 v10 = r1[lane], v11 = r1[lane + 32];
            a0.x = fmaf(v00.x, w0, a0.x); a0.y = fmaf(v00.y, w0, a0.y);
            a0.z = fmaf(v00.z, w0, a0.z); a0.w = fmaf(v00.w, w0, a0.w);
            a1.x = fmaf(v01.x, w0, a1.x); a1.y = fmaf(v01.y, w0, a1.y);
            a1.z = fmaf(v01.z, w0, a1.z); a1.w = fmaf(v01.w, w0, a1.w);
            a0.x = fmaf(v10.x, w1, a0.x); a0.y = fmaf(v10.y, w1, a0.y);
            a0.z = fmaf(v10.z, w1, a0.z); a0.w = fmaf(v10.w, w1, a0.w);
            a1.x = fmaf(v11.x, w1, a1.x); a1.y = fmaf(v11.y, w1, a1.y);
            a1.z = fmaf(v11.z, w1, a1.z); a1.w = fmaf(v11.w, w1, a1.w);
        }
        if (e < end) {
            int s0 = g_edge_src[e];
            float w0 = g_rs_out[s0];
            const float4* r0 = reinterpret_cast<const float4*>(g_h + (size_t)s0 * F);
            float4 v00 = r0[lane], v01 = r0[lane + 32];
            a0.x = fmaf(v00.x, w0, a0.x); a0.y = fmaf(v00.y, w0, a0.y);
            a0.z = fmaf(v00.z, w0, a0.z); a0.w = fmaf(v00.w, w0, a0.w);
            a1.x = fmaf(v01.x, w0, a1.x); a1.y = fmaf(v01.y, w0, a1.y);
            a1.z = fmaf(v01.z, w0, a1.z); a1.w = fmaf(v01.w, w0, a1.w);
        }

        float rs = rsqrtf((float)max(end - begin, 1));
        const float4* b4 = reinterpret_cast<const float4*>(b);
        float4 b0 = b4[lane], b1 = b4[lane + 32];

        float4 o0, o1;
        o0.x = fmaxf(fmaf(a0.x, rs, b0.x), 0.f);
        o0.y = fmaxf(fmaf(a0.y, rs, b0.y), 0.f);
        o0.z = fmaxf(fmaf(a0.z, rs, b0.z), 0.f);
        o0.w = fmaxf(fmaf(a0.w, rs, b0.w), 0.f);
        o1.x = fmaxf(fmaf(a1.x, rs, b1.x), 0.f);
        o1.y = fmaxf(fmaf(a1.y, rs, b1.y), 0.f);
        o1.z = fmaxf(fmaf(a1.z, rs, b1.z), 0.f);
        o1.w = fmaxf(fmaf(a1.w, rs, b1.w), 0.f);

        int f0 = lane << 2;
        atomicAdd(&pooled_s[f0 + 0], o0.x);
        atomicAdd(&pooled_s[f0 + 1], o0.y);
        atomicAdd(&pooled_s[f0 + 2], o0.z);
        atomicAdd(&pooled_s[f0 + 3], o0.w);
        int f1 = (lane + 32) << 2;
        atomicAdd(&pooled_s[f1 + 0], o1.x);
        atomicAdd(&pooled_s[f1 + 1], o1.y);
        atomicAdd(&pooled_s[f1 + 2], o1.z);
        atomicAdd(&pooled_s[f1 + 3], o1.w);
    }

    __syncthreads();
    if (threadIdx.x < F) atomicAdd(&g_pooled[threadIdx.x], pooled_s[threadIdx.x]);
}

// ---------------- K5: head  softmax(pooled/N @ W2 + b2) ----------------------
__global__ __launch_bounds__(64) void head_kernel(const float* __restrict__ W2,
                                                  const float* __restrict__ b2,
                                                  float* __restrict__ out, float invN) {
    __shared__ float pooled_s[F];
    __shared__ float sm[C];
    int t = threadIdx.x;
    for (int j = t; j < F; j += C) pooled_s[j] = g_pooled[j] * invN;
    __syncthreads();

    float acc = b2[t];
#pragma unroll 8
    for (int j = 0; j < F; j++) acc = fmaf(pooled_s[j], W2[(size_t)j * C + t], acc);

    sm[t] = acc;
    __syncthreads();
    float m = sm[0];
#pragma unroll
    for (int j = 1; j < C; j++) m = fmaxf(m, sm[j]);
    __syncthreads();
    float e = expf(acc - m);
    sm[t] = e;
    __syncthreads();
    float ssum = 0.f;
#pragma unroll
    for (int j = 0; j < C; j++) ssum += sm[j];
    out[t] = e / ssum;
}

// ---------------- launch -------------------------------------------------------
extern "C" void kernel_launch(void* const* d_in, const int* in_sizes, int n_in,
                              void* d_out, int out_size) {
    const float* x   = (const float*)d_in[0];
    const void*  src = d_in[1];
    const void*  dst = d_in[2];
    const float* W   = (const float*)d_in[3];
    const float* b   = (const float*)d_in[4];
    const float* W2  = (const float*)d_in[5];
    const float* b2  = (const float*)d_in[6];
    float*       out = (float*)d_out;

    const int nodes = in_sizes[0] / F;     // 100000
    const int nE    = in_sizes[1];         // 1600000
    const int nScanBlocks = (nodes + 255) / 256;

    cudaStream_t sB;
    cudaStreamCreateWithFlags(&sB, cudaStreamNonBlocking);
    cudaEvent_t evFork, evJoin;
    cudaEventCreateWithFlags(&evFork, cudaEventDisableTiming);
    cudaEventCreateWithFlags(&evJoin, cudaEventDisableTiming);

    // main: dtype probe (launch 0), then tf32 pre-conversions (1,2)
    detect_kernel<<<1, 256>>>((const unsigned int*)src);
    cudaEventRecord(evFork, 0);
    wcvt_kernel<<<(F * F / 4 + 255) / 256, 256>>>(W);
    xcvt_kernel<<<2048, 256>>>(x, (long long)nodes * F / 4);

    // main: GEMM = launch index 3 (ncu profiles this slot)
    dim3 ggrid((nodes + TBM - 1) / TBM, F / TBN);
    gemm_tc_kernel<<<ggrid, 256>>>(nodes);

    // branch B (forked after detect): zero -> degrees -> rsqrt -> CSR build
    cudaStreamWaitEvent(sB, evFork, 0);
    zero_kernel<<<256, 256, 0, sB>>>(nodes);
    deg_kernel<<<(nE + 255) / 256, 256, 0, sB>>>(src, dst, nE);
    rs_kernel<<<(nodes + 255) / 256, 256, 0, sB>>>(nodes);
    scan_a_kernel<<<nScanBlocks, 256, 0, sB>>>(nodes);
    scan_b_kernel<<<1, SCAN_BLOCKS, 0, sB>>>(nScanBlocks);
    scan_c_kernel<<<nScanBlocks, 256, 0, sB>>>(nodes);
    scatter_kernel<<<(nE + 255) / 256, 256, 0, sB>>>(src, dst, nE);
    cudaEventRecord(evJoin, sB);

    // join, then aggregate + head
    cudaStreamWaitEvent(0, evJoin, 0);
    int ablocks = (nodes + 7) / 8;
    agg_kernel<<<ablocks, 256>>>(b, nodes);
    head_kernel<<<1, C>>>(W2, b2, out, 1.0f / (float)nodes);

    cudaEventDestroy(evFork);
    cudaEventDestroy(evJoin);
    cudaStreamDestroy(sB);
}

// round 15
// speedup vs baseline: 1.0932x; 1.0932x over previous
#include <cuda_runtime.h>
#include <cstdint>

#define N_NODES 100000
#define N_EDGES 1600000
#define F 256          // IN_FEATS == H_FEATS
#define C 64           // NUM_CLASSES

// ---------------- scratch (static device globals; no allocation) -------------
__device__ int      g_deg_out[N_NODES];
__device__ int      g_deg_in[N_NODES];
__device__ float    g_rs_out[N_NODES];            // rsqrt(max(deg_out,1))
__device__ unsigned g_w32[(size_t)F * F];         // W pre-converted to tf32
__device__ float    g_h[(size_t)N_NODES * F];     // x @ W  (unscaled)
__device__ float    g_pooled[F];
__device__ int      g_is64;
// CSR-by-dst
__device__ int   g_row_ptr[N_NODES + 1];
__device__ int   g_cursor[N_NODES];
__device__ int   g_edge_src[N_EDGES];
#define SCAN_BLOCKS 1024
__device__ int   g_blocksum[SCAN_BLOCKS];
__device__ int   g_blockoff[SCAN_BLOCKS];

// ---------------- K-1: index dtype probe --------------------------------------
__global__ void detect_kernel(const unsigned int* __restrict__ words) {
    __shared__ int nonzero;
    if (threadIdx.x == 0) nonzero = 0;
    __syncthreads();
    for (int p = threadIdx.x; p < 1024; p += blockDim.x)
        if (words[2 * p + 1] != 0u) atomicOr(&nonzero, 1);
    __syncthreads();
    if (threadIdx.x == 0) g_is64 = (nonzero == 0) ? 1 : 0;
}

__device__ __forceinline__ int load_idx(const void* p, int i, int is64) {
    return is64 ? (int)((const long long*)p)[i] : ((const int*)p)[i];
}

__device__ __forceinline__ unsigned f2tf32(float f) {
    unsigned u;
    asm("cvt.rna.tf32.f32 %0, %1;" : "=r"(u) : "f"(f));
    return u;
}

// ---------------- W tf32 pre-conversion ---------------------------------------
__global__ void wcvt_kernel(const float* __restrict__ W) {
    int i = blockIdx.x * blockDim.x + threadIdx.x;   // over F*F/4
    const float4* in = reinterpret_cast<const float4*>(W);
    uint4* o = reinterpret_cast<uint4*>(g_w32);
    if (i < F * F / 4) {
        float4 v = in[i];
        uint4 u;
        u.x = f2tf32(v.x); u.y = f2tf32(v.y); u.z = f2tf32(v.z); u.w = f2tf32(v.w);
        o[i] = u;
    }
}

// ---------------- K0: zero scratch -------------------------------------------
__global__ void zero_kernel(int nodes) {
    int tid    = blockIdx.x * blockDim.x + threadIdx.x;
    int stride = gridDim.x * blockDim.x;
    for (int i = tid; i < nodes; i += stride) {
        g_deg_out[i] = 0;
        g_deg_in[i]  = 0;
    }
    if (tid < F) g_pooled[tid] = 0.f;
}

// ---------------- K1: degree counts ------------------------------------------
__global__ void deg_kernel(const void* __restrict__ src,
                           const void* __restrict__ dst, int nE) {
    int i = blockIdx.x * blockDim.x + threadIdx.x;
    int is64 = g_is64;
    if (i < nE) {
        atomicAdd(&g_deg_out[load_idx(src, i, is64)], 1);
        atomicAdd(&g_deg_in[load_idx(dst, i, is64)], 1);
    }
}

__global__ void rs_kernel(int nodes) {
    int i = blockIdx.x * blockDim.x + threadIdx.x;
    if (i < nodes) g_rs_out[i] = rsqrtf((float)max(g_deg_out[i], 1));
}

// ---------------- CSR build: 3-phase block scan of deg_in --------------------
__global__ void scan_a_kernel(int nodes) {
    __shared__ int s[256];
    int i = blockIdx.x * 256 + threadIdx.x;
    s[threadIdx.x] = (i < nodes) ? g_deg_in[i] : 0;
    __syncthreads();
#pragma unroll
    for (int off = 128; off > 0; off >>= 1) {
        if (threadIdx.x < off) s[threadIdx.x] += s[threadIdx.x + off];
        __syncthreads();
    }
    if (threadIdx.x == 0) g_blocksum[blockIdx.x] = s[0];
}

__global__ void scan_b_kernel(int nblocks) {
    __shared__ int s[SCAN_BLOCKS];
    int t = threadIdx.x;
    s[t] = (t < nblocks) ? g_blocksum[t] : 0;
    __syncthreads();
#pragma unroll
    for (int off = 1; off < SCAN_BLOCKS; off <<= 1) {
        int v = (t >= off) ? s[t - off] : 0;
        __syncthreads();
        s[t] += v;
        __syncthreads();
    }
    if (t < nblocks) g_blockoff[t] = (t == 0) ? 0 : s[t - 1];
}

__global__ void scan_c_kernel(int nodes) {
    __shared__ int s[256];
    int i = blockIdx.x * 256 + threadIdx.x;
    int t = threadIdx.x;
    int d = (i < nodes) ? g_deg_in[i] : 0;
    s[t] = d;
    __syncthreads();
#pragma unroll
    for (int off = 1; off < 256; off <<= 1) {
        int v = (t >= off) ? s[t - off] : 0;
        __syncthreads();
        s[t] += v;
        __syncthreads();
    }
    int excl = g_blockoff[blockIdx.x] + s[t] - d;
    if (i < nodes) {
        g_row_ptr[i] = excl;
        g_cursor[i]  = excl;
        if (i == nodes - 1) g_row_ptr[nodes] = excl + d;
    }
}

__global__ void scatter_kernel(const void* __restrict__ src,
                               const void* __restrict__ dst, int nE) {
    int i = blockIdx.x * blockDim.x + threadIdx.x;
    int is64 = g_is64;
    if (i < nE) {
        int d = load_idx(dst, i, is64);
        int pos = atomicAdd(&g_cursor[d], 1);
        g_edge_src[pos] = load_idx(src, i, is64);
    }
}

// ---------------- K2: TF32 tensor-core GEMM  h = x @ W -----------------------
// 128x128 block tile, BK=16 (2 k-steps of 8), 8 warps as 4(m) x 2(n).
// DOUBLE-BUFFERED smem, ONE barrier per k-tile:
//   read frags from buf[cur] -> early LDG tile k+1 -> mma (B frags loaded
//   inside ni-loop, 4 live regs) -> cvt+STS into buf[nxt] -> sync.
// A converted fp32->tf32 in the STS path; W pre-converted (g_w32).
#define TBM 128
#define TBN 128
#define TBK 16

__device__ __forceinline__ void mma_tf32(float c[4], const unsigned a[4], const unsigned b[2]) {
    asm volatile(
        "mma.sync.aligned.m16n8k8.row.col.f32.tf32.tf32.f32 "
        "{%0,%1,%2,%3}, {%4,%5,%6,%7}, {%8,%9}, {%0,%1,%2,%3};"
        : "+f"(c[0]), "+f"(c[1]), "+f"(c[2]), "+f"(c[3])
        : "r"(a[0]), "r"(a[1]), "r"(a[2]), "r"(a[3]), "r"(b[0]), "r"(b[1]));
}

__global__ __launch_bounds__(256) void gemm_tc_kernel(const float* __restrict__ x,
                                                      int M) {
    __shared__ unsigned As[2][8][4][32][2];    // 2 x 8KB
    __shared__ unsigned Bs[2][16][2][32][2];   // 2 x 8KB

    const int t      = threadIdx.x;
    const int lane   = t & 31;
    const int wid    = t >> 5;
    const int warp_m = wid & 3;
    const int warp_n = wid >> 2;
    const int bm     = blockIdx.x * TBM;
    const int bn     = blockIdx.y * TBN;

    const int aRow  = t >> 2;            // 0..63 (+64)
    const int aKc4  = (t & 3) << 2;      // 0,4,8,12
    const int bK    = t >> 5;            // 0..7 (+8)
    const int bNc4  = (t & 31) << 2;     // 0..124

    // precomputed A-store coordinates
    const int aKstep = aKc4 >> 3;
    const int aCch   = (aKc4 & 7) >> 2;

    float acc[2][8][4];
#pragma unroll
    for (int i = 0; i < 2; i++)
#pragma unroll
        for (int j = 0; j < 8; j++)
#pragma unroll
            for (int r = 0; r < 4; r++) acc[i][j][r] = 0.f;

    const int g = lane >> 2;
    const int tg = lane & 3;
    const int laneq = tg * 8 + g;

    const int nTiles = F / TBK;
    float4 pa[2];
    uint4  pb[2];

    // prologue: load tile 0
#pragma unroll
    for (int half = 0; half < 2; half++) {
        int r = aRow + half * 64;
        pa[half] = make_float4(0.f, 0.f, 0.f, 0.f);
        if (bm + r < M)
            pa[half] = *reinterpret_cast<const float4*>(x + (size_t)(bm + r) * F + 0 + aKc4);
        int k = bK + half * 8;
        pb[half] = *reinterpret_cast<const uint4*>(g_w32 + (size_t)(0 + k) * F + bn + bNc4);
    }
    // store tile 0 into buf 0
#pragma unroll
    for (int half = 0; half < 2; half++) {
        int r = aRow + half * 64;
        int m16 = r >> 4, rlo = r & 15;
        int reg = ((rlo >= 8) ? 1 : 0) + 2 * aCch;
        int lb  = (rlo & 7) * 4;
        As[0][m16][reg][lb + 0][aKstep] = f2tf32(pa[half].x);
        As[0][m16][reg][lb + 1][aKstep] = f2tf32(pa[half].y);
        As[0][m16][reg][lb + 2][aKstep] = f2tf32(pa[half].z);
        As[0][m16][reg][lb + 3][aKstep] = f2tf32(pa[half].w);
        int k = bK + half * 8;
        int kstep = k >> 3, kk = k & 7;
        int breg = (kk >= 4) ? 1 : 0;
        int tgk = kk & 3;
        int n8 = bNc4 >> 3, gb = bNc4 & 7;
        Bs[0][n8][breg][tgk * 8 + gb + 0][kstep] = pb[half].x;
        Bs[0][n8][breg][tgk * 8 + gb + 1][kstep] = pb[half].y;
        Bs[0][n8][breg][tgk * 8 + gb + 2][kstep] = pb[half].z;
        Bs[0][n8][breg][tgk * 8 + gb + 3][kstep] = pb[half].w;
    }
    __syncthreads();

    for (int kt = 0; kt < nTiles; kt++) {
        const int cur = kt & 1;
        const int nxt = cur ^ 1;

        // ---- A fragment loads from buf[cur] (8 x LDS.64) ----
        unsigned afr[2][2][4];   // [mi][kstep][reg]
#pragma unroll
        for (int mi = 0; mi < 2; mi++) {
            int m16 = warp_m * 2 + mi;
#pragma unroll
            for (int r = 0; r < 4; r++) {
                uint2 v = *reinterpret_cast<const uint2*>(&As[cur][m16][r][lane][0]);
                afr[mi][0][r] = v.x;
                afr[mi][1][r] = v.y;
            }
        }

        // ---- early gmem prefetch of tile kt+1 ----
        const bool hasNext = (kt + 1 < nTiles);
        if (hasNext) {
            const int k0 = (kt + 1) * TBK;
#pragma unroll
            for (int half = 0; half < 2; half++) {
                int r = aRow + half * 64;
                pa[half] = make_float4(0.f, 0.f, 0.f, 0.f);
                if (bm + r < M)
                    pa[half] = *reinterpret_cast<const float4*>(x + (size_t)(bm + r) * F + k0 + aKc4);
                int k = bK + half * 8;
                pb[half] = *reinterpret_cast<const uint4*>(g_w32 + (size_t)(k0 + k) * F + bn + bNc4);
            }
        }

        // ---- mma; B fragments loaded per-ni (LDS hidden under previous mmas) ----
#pragma unroll
        for (int ni = 0; ni < 8; ni++) {
            int n8 = warp_n * 8 + ni;
            unsigned bfr[2][2];   // [kstep][reg]
#pragma unroll
            for (int r = 0; r < 2; r++) {
                uint2 v = *reinterpret_cast<const uint2*>(&Bs[cur][n8][r][laneq][0]);
                bfr[0][r] = v.x;
                bfr[1][r] = v.y;
            }
#pragma unroll
            for (int ks = 0; ks < 2; ks++)
#pragma unroll
                for (int mi = 0; mi < 2; mi++)
                    mma_tf32(acc[mi][ni], afr[mi][ks], bfr[ks]);
        }

        // ---- store tile kt+1 into buf[nxt] (LDG waits hidden by mma above) ----
        if (hasNext) {
#pragma unroll
            for (int half = 0; half < 2; half++) {
                int r = aRow + half * 64;
                int m16 = r >> 4, rlo = r & 15;
                int reg = ((rlo >= 8) ? 1 : 0) + 2 * aCch;
                int lb  = (rlo & 7) * 4;
                As[nxt][m16][reg][lb + 0][aKstep] = f2tf32(pa[half].x);
                As[nxt][m16][reg][lb + 1][aKstep] = f2tf32(pa[half].y);
                As[nxt][m16][reg][lb + 2][aKstep] = f2tf32(pa[half].z);
                As[nxt][m16][reg][lb + 3][aKstep] = f2tf32(pa[half].w);
                int k = bK + half * 8;
                int kstep = k >> 3, kk = k & 7;
                int breg = (kk >= 4) ? 1 : 0;
                int tgk = kk & 3;
                int n8 = bNc4 >> 3, gb = bNc4 & 7;
                Bs[nxt][n8][breg][tgk * 8 + gb + 0][kstep] = pb[half].x;
                Bs[nxt][n8][breg][tgk * 8 + gb + 1][kstep] = pb[half].y;
                Bs[nxt][n8][breg][tgk * 8 + gb + 2][kstep] = pb[half].z;
                Bs[nxt][n8][breg][tgk * 8 + gb + 3][kstep] = pb[half].w;
            }
        }
        __syncthreads();
    }

    // ---- epilogue ----
#pragma unroll
    for (int mi = 0; mi < 2; mi++) {
        int rowA = bm + warp_m * 32 + mi * 16 + g;
        int rowB = rowA + 8;
#pragma unroll
        for (int ni = 0; ni < 8; ni++) {
            int col = bn + warp_n * 64 + ni * 8 + tg * 2;
            if (rowA < M)
                *reinterpret_cast<float2*>(g_h + (size_t)rowA * F + col) =
                    make_float2(acc[mi][ni][0], acc[mi][ni][1]);
            if (rowB < M)
                *reinterpret_cast<float2*>(g_h + (size_t)rowB * F + col) =
                    make_float2(acc[mi][ni][2], acc[mi][ni][3]);
        }
    }
}

// ---------------- K3: CSR aggregate + epilogue + pool -------------------------
__global__ __launch_bounds__(256) void agg_kernel(const float* __restrict__ b,
                                                  int nodes) {
    __shared__ float pooled_s[F];
    if (threadIdx.x < F) pooled_s[threadIdx.x] = 0.f;
    __syncthreads();

    int warp = (blockIdx.x * blockDim.x + threadIdx.x) >> 5;
    int lane = threadIdx.x & 31;

    if (warp < nodes) {
        int begin = g_row_ptr[warp];
        int end   = g_row_ptr[warp + 1];

        float4 a0 = make_float4(0.f, 0.f, 0.f, 0.f);
        float4 a1 = make_float4(0.f, 0.f, 0.f, 0.f);

        int e = begin;
        for (; e + 1 < end; e += 2) {
            int s0 = g_edge_src[e];
            int s1 = g_edge_src[e + 1];
            float w0 = g_rs_out[s0];
            float w1 = g_rs_out[s1];
            const float4* r0 = reinterpret_cast<const float4*>(g_h + (size_t)s0 * F);
            const float4* r1 = reinterpret_cast<const float4*>(g_h + (size_t)s1 * F);
            float4 v00 = r0[lane], v01 = r0[lane + 32];
            float4 v10 = r1[lane], v11 = r1[lane + 32];
            a0.x = fmaf(v00.x, w0, a0.x); a0.y = fmaf(v00.y, w0, a0.y);
            a0.z = fmaf(v00.z, w0, a0.z); a0.w = fmaf(v00.w, w0, a0.w);
            a1.x = fmaf(v01.x, w0, a1.x); a1.y = fmaf(v01.y, w0, a1.y);
            a1.z = fmaf(v01.z, w0, a1.z); a1.w = fmaf(v01.w, w0, a1.w);
            a0.x = fmaf(v10.x, w1, a0.x); a0.y = fmaf(v10.y, w1, a0.y);
            a0.z = fmaf(v10.z, w1, a0.z); a0.w = fmaf(v10.w, w1, a0.w);
            a1.x = fmaf(v11.x, w1, a1.x); a1.y = fmaf(v11.y, w1, a1.y);
            a1.z = fmaf(v11.z, w1, a1.z); a1.w = fmaf(v11.w, w1, a1.w);
        }
        if (e < end) {
            int s0 = g_edge_src[e];
            float w0 = g_rs_out[s0];
            const float4* r0 = reinterpret_cast<const float4*>(g_h + (size_t)s0 * F);
            float4 v00 = r0[lane], v01 = r0[lane + 32];
            a0.x = fmaf(v00.x, w0, a0.x); a0.y = fmaf(v00.y, w0, a0.y);
            a0.z = fmaf(v00.z, w0, a0.z); a0.w = fmaf(v00.w, w0, a0.w);
            a1.x = fmaf(v01.x, w0, a1.x); a1.y = fmaf(v01.y, w0, a1.y);
            a1.z = fmaf(v01.z, w0, a1.z); a1.w = fmaf(v01.w, w0, a1.w);
        }

        float rs = rsqrtf((float)max(end - begin, 1));
        const float4* b4 = reinterpret_cast<const float4*>(b);
        float4 b0 = b4[lane], b1 = b4[lane + 32];

        float4 o0, o1;
        o0.x = fmaxf(fmaf(a0.x, rs, b0.x), 0.f);
        o0.y = fmaxf(fmaf(a0.y, rs, b0.y), 0.f);
        o0.z = fmaxf(fmaf(a0.z, rs, b0.z), 0.f);
        o0.w = fmaxf(fmaf(a0.w, rs, b0.w), 0.f);
        o1.x = fmaxf(fmaf(a1.x, rs, b1.x), 0.f);
        o1.y = fmaxf(fmaf(a1.y, rs, b1.y), 0.f);
        o1.z = fmaxf(fmaf(a1.z, rs, b1.z), 0.f);
        o1.w = fmaxf(fmaf(a1.w, rs, b1.w), 0.f);

        int f0 = lane << 2;
        atomicAdd(&pooled_s[f0 + 0], o0.x);
        atomicAdd(&pooled_s[f0 + 1], o0.y);
        atomicAdd(&pooled_s[f0 + 2], o0.z);
        atomicAdd(&pooled_s[f0 + 3], o0.w);
        int f1 = (lane + 32) << 2;
        atomicAdd(&pooled_s[f1 + 0], o1.x);
        atomicAdd(&pooled_s[f1 + 1], o1.y);
        atomicAdd(&pooled_s[f1 + 2], o1.z);
        atomicAdd(&pooled_s[f1 + 3], o1.w);
    }

    __syncthreads();
    if (threadIdx.x < F) atomicAdd(&g_pooled[threadIdx.x], pooled_s[threadIdx.x]);
}

// ---------------- K5: head  softmax(pooled/N @ W2 + b2) ----------------------
__global__ __launch_bounds__(64) void head_kernel(const float* __restrict__ W2,
                                                  const float* __restrict__ b2,
                                                  float* __restrict__ out, float invN) {
    __shared__ float pooled_s[F];
    __shared__ float sm[C];
    int t = threadIdx.x;
    for (int j = t; j < F; j += C) pooled_s[j] = g_pooled[j] * invN;
    __syncthreads();

    float acc = b2[t];
#pragma unroll 8
    for (int j = 0; j < F; j++) acc = fmaf(pooled_s[j], W2[(size_t)j * C + t], acc);

    sm[t] = acc;
    __syncthreads();
    float m = sm[0];
#pragma unroll
    for (int j = 1; j < C; j++) m = fmaxf(m, sm[j]);
    __syncthreads();
    float e = expf(acc - m);
    sm[t] = e;
    __syncthreads();
    float ssum = 0.f;
#pragma unroll
    for (int j = 0; j < C; j++) ssum += sm[j];
    out[t] = e / ssum;
}

// ---------------- launch -------------------------------------------------------
extern "C" void kernel_launch(void* const* d_in, const int* in_sizes, int n_in,
                              void* d_out, int out_size) {
    const float* x   = (const float*)d_in[0];
    const void*  src = d_in[1];
    const void*  dst = d_in[2];
    const float* W   = (const float*)d_in[3];
    const float* b   = (const float*)d_in[4];
    const float* W2  = (const float*)d_in[5];
    const float* b2  = (const float*)d_in[6];
    float*       out = (float*)d_out;

    const int nodes = in_sizes[0] / F;     // 100000
    const int nE    = in_sizes[1];         // 1600000
    const int nScanBlocks = (nodes + 255) / 256;

    cudaStream_t sB;
    cudaStreamCreateWithFlags(&sB, cudaStreamNonBlocking);
    cudaEvent_t evFork, evJoin;
    cudaEventCreateWithFlags(&evFork, cudaEventDisableTiming);
    cudaEventCreateWithFlags(&evJoin, cudaEventDisableTiming);

    // main: detect(0), wcvt(1), zero(2) -> fork, GEMM at launch index 3
    detect_kernel<<<1, 256>>>((const unsigned int*)src);
    wcvt_kernel<<<(F * F / 4 + 255) / 256, 256>>>(W);
    zero_kernel<<<256, 256>>>(nodes);
    cudaEventRecord(evFork, 0);

    dim3 ggrid((nodes + TBM - 1) / TBM, F / TBN);
    gemm_tc_kernel<<<ggrid, 256>>>(x, nodes);

    // branch B: degrees -> rsqrt -> CSR build (overlaps GEMM on idle SMs / queues)
    cudaStreamWaitEvent(sB, evFork, 0);
    deg_kernel<<<(nE + 255) / 256, 256, 0, sB>>>(src, dst, nE);
    rs_kernel<<<(nodes + 255) / 256, 256, 0, sB>>>(nodes);
    scan_a_kernel<<<nScanBlocks, 256, 0, sB>>>(nodes);
    scan_b_kernel<<<1, SCAN_BLOCKS, 0, sB>>>(nScanBlocks);
    scan_c_kernel<<<nScanBlocks, 256, 0, sB>>>(nodes);
    scatter_kernel<<<(nE + 255) / 256, 256, 0, sB>>>(src, dst, nE);
    cudaEventRecord(evJoin, sB);

    // join, then aggregate + head
    cudaStreamWaitEvent(0, evJoin, 0);
    int ablocks = (nodes + 7) / 8;
    agg_kernel<<<ablocks, 256>>>(b, nodes);
    head_kernel<<<1, C>>>(W2, b2, out, 1.0f / (float)nodes);

    cudaEventDestroy(evFork);
    cudaEventDestroy(evJoin);
    cudaStreamDestroy(sB);
}

// round 16
// speedup vs baseline: 1.1629x; 1.0638x over previous
#include <cuda_runtime.h>
#include <cuda_bf16.h>
#include <cstdint>

#define N_NODES 100000
#define N_EDGES 1600000
#define F 256          // IN_FEATS == H_FEATS
#define C 64           // NUM_CLASSES

// ---------------- scratch (static device globals; no allocation) -------------
__device__ int      g_deg_out[N_NODES];
__device__ int      g_deg_in[N_NODES];
__device__ float    g_rs_out[N_NODES];            // rsqrt(max(deg_out,1))
__device__ unsigned g_w32[(size_t)F * F];         // W pre-converted to tf32
__device__ unsigned g_hb[(size_t)N_NODES * F / 2];// x @ W as bf16x2 pairs
__device__ float    g_pooled[F];
__device__ int      g_is64;
// CSR-by-dst
__device__ int   g_row_ptr[N_NODES + 1];
__device__ int   g_cursor[N_NODES];
__device__ int   g_edge_src[N_EDGES];
#define SCAN_BLOCKS 1024
__device__ int   g_blocksum[SCAN_BLOCKS];
__device__ int   g_blockoff[SCAN_BLOCKS];

// ---------------- K-1: index dtype probe --------------------------------------
__global__ void detect_kernel(const unsigned int* __restrict__ words) {
    __shared__ int nonzero;
    if (threadIdx.x == 0) nonzero = 0;
    __syncthreads();
    for (int p = threadIdx.x; p < 1024; p += blockDim.x)
        if (words[2 * p + 1] != 0u) atomicOr(&nonzero, 1);
    __syncthreads();
    if (threadIdx.x == 0) g_is64 = (nonzero == 0) ? 1 : 0;
}

__device__ __forceinline__ int load_idx(const void* p, int i, int is64) {
    return is64 ? (int)((const long long*)p)[i] : ((const int*)p)[i];
}

__device__ __forceinline__ unsigned f2tf32(float f) {
    unsigned u;
    asm("cvt.rna.tf32.f32 %0, %1;" : "=r"(u) : "f"(f));
    return u;
}

// ---------------- W tf32 pre-conversion ---------------------------------------
__global__ void wcvt_kernel(const float* __restrict__ W) {
    int i = blockIdx.x * blockDim.x + threadIdx.x;   // over F*F/4
    const float4* in = reinterpret_cast<const float4*>(W);
    uint4* o = reinterpret_cast<uint4*>(g_w32);
    if (i < F * F / 4) {
        float4 v = in[i];
        uint4 u;
        u.x = f2tf32(v.x); u.y = f2tf32(v.y); u.z = f2tf32(v.z); u.w = f2tf32(v.w);
        o[i] = u;
    }
}

// ---------------- K0: zero scratch -------------------------------------------
__global__ void zero_kernel(int nodes) {
    int tid    = blockIdx.x * blockDim.x + threadIdx.x;
    int stride = gridDim.x * blockDim.x;
    for (int i = tid; i < nodes; i += stride) {
        g_deg_out[i] = 0;
        g_deg_in[i]  = 0;
    }
    if (tid < F) g_pooled[tid] = 0.f;
}

// ---------------- K1: degree counts ------------------------------------------
__global__ void deg_kernel(const void* __restrict__ src,
                           const void* __restrict__ dst, int nE) {
    int i = blockIdx.x * blockDim.x + threadIdx.x;
    int is64 = g_is64;
    if (i < nE) {
        atomicAdd(&g_deg_out[load_idx(src, i, is64)], 1);
        atomicAdd(&g_deg_in[load_idx(dst, i, is64)], 1);
    }
}

__global__ void rs_kernel(int nodes) {
    int i = blockIdx.x * blockDim.x + threadIdx.x;
    if (i < nodes) g_rs_out[i] = rsqrtf((float)max(g_deg_out[i], 1));
}

// ---------------- CSR build: 3-phase block scan of deg_in --------------------
__global__ void scan_a_kernel(int nodes) {
    __shared__ int s[256];
    int i = blockIdx.x * 256 + threadIdx.x;
    s[threadIdx.x] = (i < nodes) ? g_deg_in[i] : 0;
    __syncthreads();
#pragma unroll
    for (int off = 128; off > 0; off >>= 1) {
        if (threadIdx.x < off) s[threadIdx.x] += s[threadIdx.x + off];
        __syncthreads();
    }
    if (threadIdx.x == 0) g_blocksum[blockIdx.x] = s[0];
}

__global__ void scan_b_kernel(int nblocks) {
    __shared__ int s[SCAN_BLOCKS];
    int t = threadIdx.x;
    s[t] = (t < nblocks) ? g_blocksum[t] : 0;
    __syncthreads();
#pragma unroll
    for (int off = 1; off < SCAN_BLOCKS; off <<= 1) {
        int v = (t >= off) ? s[t - off] : 0;
        __syncthreads();
        s[t] += v;
        __syncthreads();
    }
    if (t < nblocks) g_blockoff[t] = (t == 0) ? 0 : s[t - 1];
}

__global__ void scan_c_kernel(int nodes) {
    __shared__ int s[256];
    int i = blockIdx.x * 256 + threadIdx.x;
    int t = threadIdx.x;
    int d = (i < nodes) ? g_deg_in[i] : 0;
    s[t] = d;
    __syncthreads();
#pragma unroll
    for (int off = 1; off < 256; off <<= 1) {
        int v = (t >= off) ? s[t - off] : 0;
        __syncthreads();
        s[t] += v;
        __syncthreads();
    }
    int excl = g_blockoff[blockIdx.x] + s[t] - d;
    if (i < nodes) {
        g_row_ptr[i] = excl;
        g_cursor[i]  = excl;
        if (i == nodes - 1) g_row_ptr[nodes] = excl + d;
    }
}

__global__ void scatter_kernel(const void* __restrict__ src,
                               const void* __restrict__ dst, int nE) {
    int i = blockIdx.x * blockDim.x + threadIdx.x;
    int is64 = g_is64;
    if (i < nE) {
        int d = load_idx(dst, i, is64);
        int pos = atomicAdd(&g_cursor[d], 1);
        g_edge_src[pos] = load_idx(src, i, is64);
    }
}

// ---------------- K2: TF32 tensor-core GEMM  h = x @ W (bf16 output) ---------
#define TBM 128
#define TBN 128
#define TBK 16

__device__ __forceinline__ void mma_tf32(float c[4], const unsigned a[4], const unsigned b[2]) {
    asm volatile(
        "mma.sync.aligned.m16n8k8.row.col.f32.tf32.tf32.f32 "
        "{%0,%1,%2,%3}, {%4,%5,%6,%7}, {%8,%9}, {%0,%1,%2,%3};"
        : "+f"(c[0]), "+f"(c[1]), "+f"(c[2]), "+f"(c[3])
        : "r"(a[0]), "r"(a[1]), "r"(a[2]), "r"(a[3]), "r"(b[0]), "r"(b[1]));
}

__global__ __launch_bounds__(256, 2) void gemm_tc_kernel(const float* __restrict__ x,
                                                         int M) {
    __shared__ unsigned As[2][8][4][32][2];    // 2 x 8KB
    __shared__ unsigned Bs[2][16][2][32][2];   // 2 x 8KB

    const int t      = threadIdx.x;
    const int lane   = t & 31;
    const int wid    = t >> 5;
    const int warp_m = wid & 3;
    const int warp_n = wid >> 2;
    const int bm     = blockIdx.x * TBM;
    const int bn     = blockIdx.y * TBN;

    const int aRow  = t >> 2;            // 0..63 (+64)
    const int aKc4  = (t & 3) << 2;      // 0,4,8,12
    const int bK    = t >> 5;            // 0..7 (+8)
    const int bNc4  = (t & 31) << 2;     // 0..124

    const int aKstep = aKc4 >> 3;
    const int aCch   = (aKc4 & 7) >> 2;

    float acc[2][8][4];
#pragma unroll
    for (int i = 0; i < 2; i++)
#pragma unroll
        for (int j = 0; j < 8; j++)
#pragma unroll
            for (int r = 0; r < 4; r++) acc[i][j][r] = 0.f;

    const int g = lane >> 2;
    const int tg = lane & 3;
    const int laneq = tg * 8 + g;

    const int nTiles = F / TBK;
    float4 pa[2];
    uint4  pb[2];

    // prologue: load + store tile 0
#pragma unroll
    for (int half = 0; half < 2; half++) {
        int r = aRow + half * 64;
        pa[half] = make_float4(0.f, 0.f, 0.f, 0.f);
        if (bm + r < M)
            pa[half] = *reinterpret_cast<const float4*>(x + (size_t)(bm + r) * F + 0 + aKc4);
        int k = bK + half * 8;
        pb[half] = *reinterpret_cast<const uint4*>(g_w32 + (size_t)(0 + k) * F + bn + bNc4);
    }
#pragma unroll
    for (int half = 0; half < 2; half++) {
        int r = aRow + half * 64;
        int m16 = r >> 4, rlo = r & 15;
        int reg = ((rlo >= 8) ? 1 : 0) + 2 * aCch;
        int lb  = (rlo & 7) * 4;
        As[0][m16][reg][lb + 0][aKstep] = f2tf32(pa[half].x);
        As[0][m16][reg][lb + 1][aKstep] = f2tf32(pa[half].y);
        As[0][m16][reg][lb + 2][aKstep] = f2tf32(pa[half].z);
        As[0][m16][reg][lb + 3][aKstep] = f2tf32(pa[half].w);
        int k = bK + half * 8;
        int kstep = k >> 3, kk = k & 7;
        int breg = (kk >= 4) ? 1 : 0;
        int tgk = kk & 3;
        int n8 = bNc4 >> 3, gb = bNc4 & 7;
        Bs[0][n8][breg][tgk * 8 + gb + 0][kstep] = pb[half].x;
        Bs[0][n8][breg][tgk * 8 + gb + 1][kstep] = pb[half].y;
        Bs[0][n8][breg][tgk * 8 + gb + 2][kstep] = pb[half].z;
        Bs[0][n8][breg][tgk * 8 + gb + 3][kstep] = pb[half].w;
    }
    __syncthreads();

    for (int kt = 0; kt < nTiles; kt++) {
        const int cur = kt & 1;
        const int nxt = cur ^ 1;

        // ---- A fragment loads from buf[cur] ----
        unsigned afr[2][2][4];   // [mi][kstep][reg]
#pragma unroll
        for (int mi = 0; mi < 2; mi++) {
            int m16 = warp_m * 2 + mi;
#pragma unroll
            for (int r = 0; r < 4; r++) {
                uint2 v = *reinterpret_cast<const uint2*>(&As[cur][m16][r][lane][0]);
                afr[mi][0][r] = v.x;
                afr[mi][1][r] = v.y;
            }
        }

        // ---- early gmem prefetch of tile kt+1 ----
        const bool hasNext = (kt + 1 < nTiles);
        if (hasNext) {
            const int k0 = (kt + 1) * TBK;
#pragma unroll
            for (int half = 0; half < 2; half++) {
                int r = aRow + half * 64;
                pa[half] = make_float4(0.f, 0.f, 0.f, 0.f);
                if (bm + r < M)
                    pa[half] = *reinterpret_cast<const float4*>(x + (size_t)(bm + r) * F + k0 + aKc4);
                int k = bK + half * 8;
                pb[half] = *reinterpret_cast<const uint4*>(g_w32 + (size_t)(k0 + k) * F + bn + bNc4);
            }
        }

        // ---- mma; B fragments register-double-buffered across ni ----
        unsigned bfr[2][2][2];   // [parity][kstep][reg]
        {
            int n8 = warp_n * 8;
#pragma unroll
            for (int r = 0; r < 2; r++) {
                uint2 v = *reinterpret_cast<const uint2*>(&Bs[cur][n8][r][laneq][0]);
                bfr[0][0][r] = v.x;
                bfr[0][1][r] = v.y;
            }
        }
#pragma unroll
        for (int ni = 0; ni < 8; ni++) {
            const int p = ni & 1;
            if (ni < 7) {
                int n8 = warp_n * 8 + ni + 1;
#pragma unroll
                for (int r = 0; r < 2; r++) {
                    uint2 v = *reinterpret_cast<const uint2*>(&Bs[cur][n8][r][laneq][0]);
                    bfr[p ^ 1][0][r] = v.x;
                    bfr[p ^ 1][1][r] = v.y;
                }
            }
#pragma unroll
            for (int ks = 0; ks < 2; ks++)
#pragma unroll
                for (int mi = 0; mi < 2; mi++)
                    mma_tf32(acc[mi][ni], afr[mi][ks], bfr[p][ks]);
        }

        // ---- store tile kt+1 into buf[nxt] ----
        if (hasNext) {
#pragma unroll
            for (int half = 0; half < 2; half++) {
                int r = aRow + half * 64;
                int m16 = r >> 4, rlo = r & 15;
                int reg = ((rlo >= 8) ? 1 : 0) + 2 * aCch;
                int lb  = (rlo & 7) * 4;
                As[nxt][m16][reg][lb + 0][aKstep] = f2tf32(pa[half].x);
                As[nxt][m16][reg][lb + 1][aKstep] = f2tf32(pa[half].y);
                As[nxt][m16][reg][lb + 2][aKstep] = f2tf32(pa[half].z);
                As[nxt][m16][reg][lb + 3][aKstep] = f2tf32(pa[half].w);
                int k = bK + half * 8;
                int kstep = k >> 3, kk = k & 7;
                int breg = (kk >= 4) ? 1 : 0;
                int tgk = kk & 3;
                int n8 = bNc4 >> 3, gb = bNc4 & 7;
                Bs[nxt][n8][breg][tgk * 8 + gb + 0][kstep] = pb[half].x;
                Bs[nxt][n8][breg][tgk * 8 + gb + 1][kstep] = pb[half].y;
                Bs[nxt][n8][breg][tgk * 8 + gb + 2][kstep] = pb[half].z;
                Bs[nxt][n8][breg][tgk * 8 + gb + 3][kstep] = pb[half].w;
            }
        }
        __syncthreads();
    }

    // ---- epilogue: pack fp32 pairs -> bf16x2, STG.32 ----
#pragma unroll
    for (int mi = 0; mi < 2; mi++) {
        int rowA = bm + warp_m * 32 + mi * 16 + g;
        int rowB = rowA + 8;
#pragma unroll
        for (int ni = 0; ni < 8; ni++) {
            int col = bn + warp_n * 64 + ni * 8 + tg * 2;   // even
            if (rowA < M) {
                __nv_bfloat162 pA = __floats2bfloat162_rn(acc[mi][ni][0], acc[mi][ni][1]);
                g_hb[(size_t)rowA * (F / 2) + (col >> 1)] = *reinterpret_cast<unsigned*>(&pA);
            }
            if (rowB < M) {
                __nv_bfloat162 pB = __floats2bfloat162_rn(acc[mi][ni][2], acc[mi][ni][3]);
                g_hb[(size_t)rowB * (F / 2) + (col >> 1)] = *reinterpret_cast<unsigned*>(&pB);
            }
        }
    }
}

// ---------------- K3: CSR aggregate (bf16 gather) + epilogue + pool -----------
__device__ __forceinline__ void accum8(float a[8], uint4 v, float w) {
    float2 p;
    p = __bfloat1622float2(*reinterpret_cast<__nv_bfloat162*>(&v.x));
    a[0] = fmaf(p.x, w, a[0]); a[1] = fmaf(p.y, w, a[1]);
    p = __bfloat1622float2(*reinterpret_cast<__nv_bfloat162*>(&v.y));
    a[2] = fmaf(p.x, w, a[2]); a[3] = fmaf(p.y, w, a[3]);
    p = __bfloat1622float2(*reinterpret_cast<__nv_bfloat162*>(&v.z));
    a[4] = fmaf(p.x, w, a[4]); a[5] = fmaf(p.y, w, a[5]);
    p = __bfloat1622float2(*reinterpret_cast<__nv_bfloat162*>(&v.w));
    a[6] = fmaf(p.x, w, a[6]); a[7] = fmaf(p.y, w, a[7]);
}

__global__ __launch_bounds__(256) void agg_kernel(const float* __restrict__ b,
                                                  int nodes) {
    __shared__ float pooled_s[F];
    if (threadIdx.x < F) pooled_s[threadIdx.x] = 0.f;
    __syncthreads();

    int warp = (blockIdx.x * blockDim.x + threadIdx.x) >> 5;
    int lane = threadIdx.x & 31;

    if (warp < nodes) {
        int begin = g_row_ptr[warp];
        int end   = g_row_ptr[warp + 1];

        float a[8] = {0.f, 0.f, 0.f, 0.f, 0.f, 0.f, 0.f, 0.f};
        const uint4* hb4 = reinterpret_cast<const uint4*>(g_hb);   // 32 uint4 per row

        int e = begin;
        for (; e + 1 < end; e += 2) {
            int s0 = g_edge_src[e];
            int s1 = g_edge_src[e + 1];
            float w0 = g_rs_out[s0];
            float w1 = g_rs_out[s1];
            uint4 v0 = hb4[(size_t)s0 * 32 + lane];
            uint4 v1 = hb4[(size_t)s1 * 32 + lane];
            accum8(a, v0, w0);
            accum8(a, v1, w1);
        }
        if (e < end) {
            int s0 = g_edge_src[e];
            float w0 = g_rs_out[s0];
            uint4 v0 = hb4[(size_t)s0 * 32 + lane];
            accum8(a, v0, w0);
        }

        float rs = rsqrtf((float)max(end - begin, 1));
        const float4* b4 = reinterpret_cast<const float4*>(b);
        float4 b0 = b4[lane * 2];       // features lane*8 .. +3
        float4 b1 = b4[lane * 2 + 1];   // features lane*8+4 .. +7

        float o[8];
        o[0] = fmaxf(fmaf(a[0], rs, b0.x), 0.f);
        o[1] = fmaxf(fmaf(a[1], rs, b0.y), 0.f);
        o[2] = fmaxf(fmaf(a[2], rs, b0.z), 0.f);
        o[3] = fmaxf(fmaf(a[3], rs, b0.w), 0.f);
        o[4] = fmaxf(fmaf(a[4], rs, b1.x), 0.f);
        o[5] = fmaxf(fmaf(a[5], rs, b1.y), 0.f);
        o[6] = fmaxf(fmaf(a[6], rs, b1.z), 0.f);
        o[7] = fmaxf(fmaf(a[7], rs, b1.w), 0.f);

        int f0 = lane << 3;
#pragma unroll
        for (int j = 0; j < 8; j++) atomicAdd(&pooled_s[f0 + j], o[j]);
    }

    __syncthreads();
    if (threadIdx.x < F) atomicAdd(&g_pooled[threadIdx.x], pooled_s[threadIdx.x]);
}

// ---------------- K5: head  softmax(pooled/N @ W2 + b2) ----------------------
__global__ __launch_bounds__(64) void head_kernel(const float* __restrict__ W2,
                                                  const float* __restrict__ b2,
                                                  float* __restrict__ out, float invN) {
    __shared__ float pooled_s[F];
    __shared__ float sm[C];
    int t = threadIdx.x;
    for (int j = t; j < F; j += C) pooled_s[j] = g_pooled[j] * invN;
    __syncthreads();

    float acc = b2[t];
#pragma unroll 8
    for (int j = 0; j < F; j++) acc = fmaf(pooled_s[j], W2[(size_t)j * C + t], acc);

    sm[t] = acc;
    __syncthreads();
    float m = sm[0];
#pragma unroll
    for (int j = 1; j < C; j++) m = fmaxf(m, sm[j]);
    __syncthreads();
    float e = expf(acc - m);
    sm[t] = e;
    __syncthreads();
    float ssum = 0.f;
#pragma unroll
    for (int j = 0; j < C; j++) ssum += sm[j];
    out[t] = e / ssum;
}

// ---------------- launch -------------------------------------------------------
extern "C" void kernel_launch(void* const* d_in, const int* in_sizes, int n_in,
                              void* d_out, int out_size) {
    const float* x   = (const float*)d_in[0];
    const void*  src = d_in[1];
    const void*  dst = d_in[2];
    const float* W   = (const float*)d_in[3];
    const float* b   = (const float*)d_in[4];
    const float* W2  = (const float*)d_in[5];
    const float* b2  = (const float*)d_in[6];
    float*       out = (float*)d_out;

    const int nodes = in_sizes[0] / F;     // 100000
    const int nE    = in_sizes[1];         // 1600000
    const int nScanBlocks = (nodes + 255) / 256;

    cudaStream_t sB;
    cudaStreamCreateWithFlags(&sB, cudaStreamNonBlocking);
    cudaEvent_t evFork, evJoin;
    cudaEventCreateWithFlags(&evFork, cudaEventDisableTiming);
    cudaEventCreateWithFlags(&evJoin, cudaEventDisableTiming);

    // main: detect(0), wcvt(1), zero(2) -> fork, GEMM at launch index 3
    detect_kernel<<<1, 256>>>((const unsigned int*)src);
    wcvt_kernel<<<(F * F / 4 + 255) / 256, 256>>>(W);
    zero_kernel<<<256, 256>>>(nodes);
    cudaEventRecord(evFork, 0);

    dim3 ggrid((nodes + TBM - 1) / TBM, F / TBN);
    gemm_tc_kernel<<<ggrid, 256>>>(x, nodes);

    // branch B: degrees -> rsqrt -> CSR build (overlaps GEMM)
    cudaStreamWaitEvent(sB, evFork, 0);
    deg_kernel<<<(nE + 255) / 256, 256, 0, sB>>>(src, dst, nE);
    rs_kernel<<<(nodes + 255) / 256, 256, 0, sB>>>(nodes);
    scan_a_kernel<<<nScanBlocks, 256, 0, sB>>>(nodes);
    scan_b_kernel<<<1, SCAN_BLOCKS, 0, sB>>>(nScanBlocks);
    scan_c_kernel<<<nScanBlocks, 256, 0, sB>>>(nodes);
    scatter_kernel<<<(nE + 255) / 256, 256, 0, sB>>>(src, dst, nE);
    cudaEventRecord(evJoin, sB);

    // join, then aggregate + head
    cudaStreamWaitEvent(0, evJoin, 0);
    int ablocks = (nodes + 7) / 8;
    agg_kernel<<<ablocks, 256>>>(b, nodes);
    head_kernel<<<1, C>>>(W2, b2, out, 1.0f / (float)nodes);

    cudaEventDestroy(evFork);
    cudaEventDestroy(evJoin);
    cudaStreamDestroy(sB);
}

// round 17
// speedup vs baseline: 1.6847x; 1.4487x over previous
#include <cuda_runtime.h>
#include <cuda_bf16.h>
#include <cstdint>

#define N_NODES 100000
#define N_EDGES 1600000
#define F 256          // IN_FEATS == H_FEATS
#define C 64           // NUM_CLASSES

// ---------------- scratch (static device globals; no allocation) -------------
__device__ int      g_deg_out[N_NODES];
__device__ int      g_deg_in[N_NODES];
__device__ float    g_rs_out[N_NODES];            // rsqrt(max(deg_out,1))
__device__ unsigned g_wb[(size_t)F * F / 2];      // W as bf16x2, fragment-permuted
__device__ unsigned g_hb[(size_t)N_NODES * F / 2];// x @ W as bf16x2 pairs
__device__ float    g_pooled[F];
__device__ int      g_is64;
// CSR-by-dst
__device__ int   g_row_ptr[N_NODES + 1];
__device__ int   g_cursor[N_NODES];
__device__ int   g_edge_src[N_EDGES];
#define SCAN_BLOCKS 1024
__device__ int   g_blocksum[SCAN_BLOCKS];
__device__ int   g_blockoff[SCAN_BLOCKS];

// ---------------- K-1: index dtype probe --------------------------------------
__global__ void detect_kernel(const unsigned int* __restrict__ words) {
    __shared__ int nonzero;
    if (threadIdx.x == 0) nonzero = 0;
    __syncthreads();
    for (int p = threadIdx.x; p < 1024; p += blockDim.x)
        if (words[2 * p + 1] != 0u) atomicOr(&nonzero, 1);
    __syncthreads();
    if (threadIdx.x == 0) g_is64 = (nonzero == 0) ? 1 : 0;
}

__device__ __forceinline__ int load_idx(const void* p, int i, int is64) {
    return is64 ? (int)((const long long*)p)[i] : ((const int*)p)[i];
}

__device__ __forceinline__ unsigned packbf2(float lo, float hi) {
    __nv_bfloat162 p = __floats2bfloat162_rn(lo, hi);
    return *reinterpret_cast<unsigned*>(&p);
}

// ---------------- W bf16 pre-conversion into fragment-permuted layout ---------
// Layout: word idx = ((((kt*2 + bnT)*16 + n8l)*32 + lane)*2 + r)
//   lane: g=lane>>2 (col within n8), tg=lane&3
//   r=0: k-pair (16kt + 2tg, +1); r=1: k-pair (16kt + 8 + 2tg, +1); n = 128bnT + 8n8l + g
__global__ void wcvt_kernel(const float* __restrict__ W) {
    int i = blockIdx.x * blockDim.x + threadIdx.x;   // over F*F/2 = 32768 words
    if (i >= F * F / 2) return;
    int r    = i & 1;
    int lane = (i >> 1) & 31;
    int n8l  = (i >> 6) & 15;
    int bnT  = (i >> 10) & 1;
    int kt   = i >> 11;
    int g2   = lane >> 2;
    int tg   = lane & 3;
    int k    = kt * 16 + tg * 2 + (r ? 8 : 0);
    int n    = bnT * 128 + n8l * 8 + g2;
    g_wb[i] = packbf2(W[(size_t)k * F + n], W[(size_t)(k + 1) * F + n]);
}

// ---------------- K0: zero scratch -------------------------------------------
__global__ void zero_kernel(int nodes) {
    int tid    = blockIdx.x * blockDim.x + threadIdx.x;
    int stride = gridDim.x * blockDim.x;
    for (int i = tid; i < nodes; i += stride) {
        g_deg_out[i] = 0;
        g_deg_in[i]  = 0;
    }
    if (tid < F) g_pooled[tid] = 0.f;
}

// ---------------- K1: degree counts ------------------------------------------
__global__ void deg_kernel(const void* __restrict__ src,
                           const void* __restrict__ dst, int nE) {
    int i = blockIdx.x * blockDim.x + threadIdx.x;
    int is64 = g_is64;
    if (i < nE) {
        atomicAdd(&g_deg_out[load_idx(src, i, is64)], 1);
        atomicAdd(&g_deg_in[load_idx(dst, i, is64)], 1);
    }
}

__global__ void rs_kernel(int nodes) {
    int i = blockIdx.x * blockDim.x + threadIdx.x;
    if (i < nodes) g_rs_out[i] = rsqrtf((float)max(g_deg_out[i], 1));
}

// ---------------- CSR build: 3-phase block scan of deg_in --------------------
__global__ void scan_a_kernel(int nodes) {
    __shared__ int s[256];
    int i = blockIdx.x * 256 + threadIdx.x;
    s[threadIdx.x] = (i < nodes) ? g_deg_in[i] : 0;
    __syncthreads();
#pragma unroll
    for (int off = 128; off > 0; off >>= 1) {
        if (threadIdx.x < off) s[threadIdx.x] += s[threadIdx.x + off];
        __syncthreads();
    }
    if (threadIdx.x == 0) g_blocksum[blockIdx.x] = s[0];
}

__global__ void scan_b_kernel(int nblocks) {
    __shared__ int s[SCAN_BLOCKS];
    int t = threadIdx.x;
    s[t] = (t < nblocks) ? g_blocksum[t] : 0;
    __syncthreads();
#pragma unroll
    for (int off = 1; off < SCAN_BLOCKS; off <<= 1) {
        int v = (t >= off) ? s[t - off] : 0;
        __syncthreads();
        s[t] += v;
        __syncthreads();
    }
    if (t < nblocks) g_blockoff[t] = (t == 0) ? 0 : s[t - 1];
}

__global__ void scan_c_kernel(int nodes) {
    __shared__ int s[256];
    int i = blockIdx.x * 256 + threadIdx.x;
    int t = threadIdx.x;
    int d = (i < nodes) ? g_deg_in[i] : 0;
    s[t] = d;
    __syncthreads();
#pragma unroll
    for (int off = 1; off < 256; off <<= 1) {
        int v = (t >= off) ? s[t - off] : 0;
        __syncthreads();
        s[t] += v;
        __syncthreads();
    }
    int excl = g_blockoff[blockIdx.x] + s[t] - d;
    if (i < nodes) {
        g_row_ptr[i] = excl;
        g_cursor[i]  = excl;
        if (i == nodes - 1) g_row_ptr[nodes] = excl + d;
    }
}

__global__ void scatter_kernel(const void* __restrict__ src,
                               const void* __restrict__ dst, int nE) {
    int i = blockIdx.x * blockDim.x + threadIdx.x;
    int is64 = g_is64;
    if (i < nE) {
        int d = load_idx(dst, i, is64);
        int pos = atomicAdd(&g_cursor[d], 1);
        g_edge_src[pos] = load_idx(src, i, is64);
    }
}

// ---------------- K2: BF16 tensor-core GEMM  h = x @ W (bf16 output) ---------
// 128x128 block tile, BK=16 = ONE m16n8k16 k-step. 8 warps as 4(m) x 2(n).
// A: fp32 gmem -> pack bf16x2 -> fragment-permuted smem (4 STS.32/thread/tile),
//    frag load = 2 x LDS.128 per warp.
// B: pre-permuted bf16 gmem chunk -> straight copy (1 LDG.128 + 1 STS.128),
//    frag load = LDS.64 per ni.
#define TBM 128
#define TBN 128
#define TBK 16

__device__ __forceinline__ void mma_bf16(float c[4], const unsigned a[4], const unsigned b[2]) {
    asm volatile(
        "mma.sync.aligned.m16n8k16.row.col.f32.bf16.bf16.f32 "
        "{%0,%1,%2,%3}, {%4,%5,%6,%7}, {%8,%9}, {%0,%1,%2,%3};"
        : "+f"(c[0]), "+f"(c[1]), "+f"(c[2]), "+f"(c[3])
        : "r"(a[0]), "r"(a[1]), "r"(a[2]), "r"(a[3]), "r"(b[0]), "r"(b[1]));
}

__global__ __launch_bounds__(256, 2) void gemm_tc_kernel(const float* __restrict__ x,
                                                         int M) {
    // A perm: [buf][m16(8)][lane(32)][reg(4)]  uint32  -> 4KB per buf
    // B perm: [buf][n8(16)][lane(32)][reg(2)]  uint32  -> 4KB per buf
    __shared__ unsigned As[2][8][32][4];
    __shared__ unsigned Bs[2][16][32][2];

    const int t      = threadIdx.x;
    const int lane   = t & 31;
    const int wid    = t >> 5;
    const int warp_m = wid & 3;
    const int warp_n = wid >> 2;
    const int bm     = blockIdx.x * TBM;
    const int bnT    = blockIdx.y;            // 0 or 1 (TBN=128)

    // A staging map: thread covers rows aRow, aRow+64; floats k = aKc4..aKc4+3
    const int aRow  = t >> 2;            // 0..63
    const int aKc4  = (t & 3) << 2;      // 0,4,8,12
    const int w0    = aKc4 >> 1;         // word index 0,2,4,6
    const int tg0   = w0 & 3;            // tg of word0
    const int tg1   = (w0 + 1) & 3;      // tg of word1
    const int khig  = (aKc4 >= 8) ? 2 : 0;

    float acc[2][8][4];
#pragma unroll
    for (int i = 0; i < 2; i++)
#pragma unroll
        for (int j = 0; j < 8; j++)
#pragma unroll
            for (int r = 0; r < 4; r++) acc[i][j][r] = 0.f;

    const int g = lane >> 2;
    const int tg = lane & 3;

    const int nTiles = F / TBK;          // 16
    float4 pa[2];
    uint4  pbv;

    // B chunk base for this block: word offset ((kt*2 + bnT) << 10)
    const uint4* wb4 = reinterpret_cast<const uint4*>(g_wb);

    // ---- prologue: load tile 0 ----
#pragma unroll
    for (int half = 0; half < 2; half++) {
        int r = aRow + half * 64;
        pa[half] = make_float4(0.f, 0.f, 0.f, 0.f);
        if (bm + r < M)
            pa[half] = *reinterpret_cast<const float4*>(x + (size_t)(bm + r) * F + 0 + aKc4);
    }
    pbv = wb4[((0 * 2 + bnT) << 8) + t];     // 256 uint4 per chunk, one per thread

    // store tile 0 into buf 0
#pragma unroll
    for (int half = 0; half < 2; half++) {
        int r = aRow + half * 64;
        int m16 = r >> 4;
        int reg = (((r & 15) >= 8) ? 1 : 0) + khig;
        int lb  = (r & 7) * 4;
        As[0][m16][lb + tg0][reg] = packbf2(pa[half].x, pa[half].y);
        As[0][m16][lb + tg1][reg] = packbf2(pa[half].z, pa[half].w);
    }
    *reinterpret_cast<uint4*>(&Bs[0][0][0][0] + t * 4) = pbv;
    __syncthreads();

    for (int kt = 0; kt < nTiles; kt++) {
        const int cur = kt & 1;
        const int nxt = cur ^ 1;

        // ---- A fragment loads: 2 x LDS.128 ----
        unsigned afr[2][4];
#pragma unroll
        for (int mi = 0; mi < 2; mi++) {
            int m16 = warp_m * 2 + mi;
            uint4 v = *reinterpret_cast<const uint4*>(&As[cur][m16][lane][0]);
            afr[mi][0] = v.x; afr[mi][1] = v.y; afr[mi][2] = v.z; afr[mi][3] = v.w;
        }

        // ---- early gmem prefetch of tile kt+1 ----
        const bool hasNext = (kt + 1 < nTiles);
        if (hasNext) {
            const int k0 = (kt + 1) * TBK;
#pragma unroll
            for (int half = 0; half < 2; half++) {
                int r = aRow + half * 64;
                pa[half] = make_float4(0.f, 0.f, 0.f, 0.f);
                if (bm + r < M)
                    pa[half] = *reinterpret_cast<const float4*>(x + (size_t)(bm + r) * F + k0 + aKc4);
            }
            pbv = wb4[(((kt + 1) * 2 + bnT) << 8) + t];
        }

        // ---- mma: 8 ni x 2 mi, B frag per ni (LDS.64) ----
#pragma unroll
        for (int ni = 0; ni < 8; ni++) {
            int n8 = warp_n * 8 + ni;
            uint2 bv = *reinterpret_cast<const uint2*>(&Bs[cur][n8][lane][0]);
            unsigned bfr[2] = {bv.x, bv.y};
#pragma unroll
            for (int mi = 0; mi < 2; mi++)
                mma_bf16(acc[mi][ni], afr[mi], bfr);
        }

        // ---- store tile kt+1 into buf[nxt] ----
        if (hasNext) {
#pragma unroll
            for (int half = 0; half < 2; half++) {
                int r = aRow + half * 64;
                int m16 = r >> 4;
                int reg = (((r & 15) >= 8) ? 1 : 0) + khig;
                int lb  = (r & 7) * 4;
                As[nxt][m16][lb + tg0][reg] = packbf2(pa[half].x, pa[half].y);
                As[nxt][m16][lb + tg1][reg] = packbf2(pa[half].z, pa[half].w);
            }
            *reinterpret_cast<uint4*>(&Bs[nxt][0][0][0] + t * 4) = pbv;
        }
        __syncthreads();
    }

    // ---- epilogue: pack fp32 pairs -> bf16x2, STG.32 ----
    const int bn = bnT * TBN;
#pragma unroll
    for (int mi = 0; mi < 2; mi++) {
        int rowA = bm + warp_m * 32 + mi * 16 + g;
        int rowB = rowA + 8;
#pragma unroll
        for (int ni = 0; ni < 8; ni++) {
            int col = bn + warp_n * 64 + ni * 8 + tg * 2;
            if (rowA < M)
                g_hb[(size_t)rowA * (F / 2) + (col >> 1)] = packbf2(acc[mi][ni][0], acc[mi][ni][1]);
            if (rowB < M)
                g_hb[(size_t)rowB * (F / 2) + (col >> 1)] = packbf2(acc[mi][ni][2], acc[mi][ni][3]);
        }
    }
}

// ---------------- K3: CSR aggregate (bf16 gather) + epilogue + pool -----------
__device__ __forceinline__ void accum8(float a[8], uint4 v, float w) {
    float2 p;
    p = __bfloat1622float2(*reinterpret_cast<__nv_bfloat162*>(&v.x));
    a[0] = fmaf(p.x, w, a[0]); a[1] = fmaf(p.y, w, a[1]);
    p = __bfloat1622float2(*reinterpret_cast<__nv_bfloat162*>(&v.y));
    a[2] = fmaf(p.x, w, a[2]); a[3] = fmaf(p.y, w, a[3]);
    p = __bfloat1622float2(*reinterpret_cast<__nv_bfloat162*>(&v.z));
    a[4] = fmaf(p.x, w, a[4]); a[5] = fmaf(p.y, w, a[5]);
    p = __bfloat1622float2(*reinterpret_cast<__nv_bfloat162*>(&v.w));
    a[6] = fmaf(p.x, w, a[6]); a[7] = fmaf(p.y, w, a[7]);
}

__global__ __launch_bounds__(256) void agg_kernel(const float* __restrict__ b,
                                                  int nodes) {
    __shared__ float pooled_s[F];
    if (threadIdx.x < F) pooled_s[threadIdx.x] = 0.f;
    __syncthreads();

    int warp = (blockIdx.x * blockDim.x + threadIdx.x) >> 5;
    int lane = threadIdx.x & 31;

    if (warp < nodes) {
        int begin = g_row_ptr[warp];
        int end   = g_row_ptr[warp + 1];

        float a[8] = {0.f, 0.f, 0.f, 0.f, 0.f, 0.f, 0.f, 0.f};
        const uint4* hb4 = reinterpret_cast<const uint4*>(g_hb);   // 32 uint4 per row

        int e = begin;
        for (; e + 1 < end; e += 2) {
            int s0 = g_edge_src[e];
            int s1 = g_edge_src[e + 1];
            float w0 = g_rs_out[s0];
            float w1 = g_rs_out[s1];
            uint4 v0 = hb4[(size_t)s0 * 32 + lane];
            uint4 v1 = hb4[(size_t)s1 * 32 + lane];
            accum8(a, v0, w0);
            accum8(a, v1, w1);
        }
        if (e < end) {
            int s0 = g_edge_src[e];
            float w0 = g_rs_out[s0];
            uint4 v0 = hb4[(size_t)s0 * 32 + lane];
            accum8(a, v0, w0);
        }

        float rs = rsqrtf((float)max(end - begin, 1));
        const float4* b4 = reinterpret_cast<const float4*>(b);
        float4 b0 = b4[lane * 2];
        float4 b1 = b4[lane * 2 + 1];

        float o[8];
        o[0] = fmaxf(fmaf(a[0], rs, b0.x), 0.f);
        o[1] = fmaxf(fmaf(a[1], rs, b0.y), 0.f);
        o[2] = fmaxf(fmaf(a[2], rs, b0.z), 0.f);
        o[3] = fmaxf(fmaf(a[3], rs, b0.w), 0.f);
        o[4] = fmaxf(fmaf(a[4], rs, b1.x), 0.f);
        o[5] = fmaxf(fmaf(a[5], rs, b1.y), 0.f);
        o[6] = fmaxf(fmaf(a[6], rs, b1.z), 0.f);
        o[7] = fmaxf(fmaf(a[7], rs, b1.w), 0.f);

        int f0 = lane << 3;
#pragma unroll
        for (int j = 0; j < 8; j++) atomicAdd(&pooled_s[f0 + j], o[j]);
    }

    __syncthreads();
    if (threadIdx.x < F) atomicAdd(&g_pooled[threadIdx.x], pooled_s[threadIdx.x]);
}

// ---------------- K5: head  softmax(pooled/N @ W2 + b2) ----------------------
__global__ __launch_bounds__(64) void head_kernel(const float* __restrict__ W2,
                                                  const float* __restrict__ b2,
                                                  float* __restrict__ out, float invN) {
    __shared__ float pooled_s[F];
    __shared__ float sm[C];
    int t = threadIdx.x;
    for (int j = t; j < F; j += C) pooled_s[j] = g_pooled[j] * invN;
    __syncthreads();

    float acc = b2[t];
#pragma unroll 8
    for (int j = 0; j < F; j++) acc = fmaf(pooled_s[j], W2[(size_t)j * C + t], acc);

    sm[t] = acc;
    __syncthreads();
    float m = sm[0];
#pragma unroll
    for (int j = 1; j < C; j++) m = fmaxf(m, sm[j]);
    __syncthreads();
    float e = expf(acc - m);
    sm[t] = e;
    __syncthreads();
    float ssum = 0.f;
#pragma unroll
    for (int j = 0; j < C; j++) ssum += sm[j];
    out[t] = e / ssum;
}

// ---------------- launch -------------------------------------------------------
extern "C" void kernel_launch(void* const* d_in, const int* in_sizes, int n_in,
                              void* d_out, int out_size) {
    const float* x   = (const float*)d_in[0];
    const void*  src = d_in[1];
    const void*  dst = d_in[2];
    const float* W   = (const float*)d_in[3];
    const float* b   = (const float*)d_in[4];
    const float* W2  = (const float*)d_in[5];
    const float* b2  = (const float*)d_in[6];
    float*       out = (float*)d_out;

    const int nodes = in_sizes[0] / F;     // 100000
    const int nE    = in_sizes[1];         // 1600000
    const int nScanBlocks = (nodes + 255) / 256;

    cudaStream_t sB;
    cudaStreamCreateWithFlags(&sB, cudaStreamNonBlocking);
    cudaEvent_t evFork, evJoin;
    cudaEventCreateWithFlags(&evFork, cudaEventDisableTiming);
    cudaEventCreateWithFlags(&evJoin, cudaEventDisableTiming);

    // main: detect(0), wcvt(1), zero(2) -> fork, GEMM at launch index 3
    detect_kernel<<<1, 256>>>((const unsigned int*)src);
    wcvt_kernel<<<(F * F / 2 + 255) / 256, 256>>>(W);
    zero_kernel<<<256, 256>>>(nodes);
    cudaEventRecord(evFork, 0);

    dim3 ggrid((nodes + TBM - 1) / TBM, F / TBN);
    gemm_tc_kernel<<<ggrid, 256>>>(x, nodes);

    // branch B: degrees -> rsqrt -> CSR build (overlaps GEMM)
    cudaStreamWaitEvent(sB, evFork, 0);
    deg_kernel<<<(nE + 255) / 256, 256, 0, sB>>>(src, dst, nE);
    rs_kernel<<<(nodes + 255) / 256, 256, 0, sB>>>(nodes);
    scan_a_kernel<<<nScanBlocks, 256, 0, sB>>>(nodes);
    scan_b_kernel<<<1, SCAN_BLOCKS, 0, sB>>>(nScanBlocks);
    scan_c_kernel<<<nScanBlocks, 256, 0, sB>>>(nodes);
    scatter_kernel<<<(nE + 255) / 256, 256, 0, sB>>>(src, dst, nE);
    cudaEventRecord(evJoin, sB);

    // join, then aggregate + head
    cudaStreamWaitEvent(0, evJoin, 0);
    int ablocks = (nodes + 7) / 8;
    agg_kernel<<<ablocks, 256>>>(b, nodes);
    head_kernel<<<1, C>>>(W2, b2, out, 1.0f / (float)nodes);

    cudaEventDestroy(evFork);
    cudaEventDestroy(evJoin);
    cudaStreamDestroy(sB);
}